// round 1
// baseline (speedup 1.0000x reference)
#include <cuda_runtime.h>

// GraphConv: out[b,k,o] = relu( inv_cnt * ( sum_n valid * (feats[b,idx]·W_feat[o] )
//                               + srel·W_rel[o] ) + bias[o] )
// Shapes (fixed by problem): B=8, P=K=16384, N=16, IN=64, REL=3, OUT=64.
//
// Mapping: 16 lanes per output row (each lane owns a float4 of 4 channels),
// 2 rows per warp, 8 warps (256 thr) per block, each block loops over 8
// chunks of 16 rows. Gathers are coalesced 256B per half-warp LDG.128.
// W is staged transposed in SMEM (Wt[c][o]) so the 67x64 per-row GEMM is
// LDS.128 conflict-free; the row-sum lives in SMEM (broadcast reads).

#define LOG2_K 14           // K = 16384
#define THREADS 256
#define CHUNKS_PER_BLOCK 8
#define ROWS_PER_CHUNK 16   // 8 warps * 2 rows

__global__ __launch_bounds__(THREADS)
void graphconv_kernel(const float* __restrict__ feats,
                      const int*   __restrict__ n_idxs,
                      const float* __restrict__ nrel,
                      const int*   __restrict__ nvalid,
                      const float* __restrict__ W,     // [64][67]
                      const float* __restrict__ bias,  // [64]
                      float*       __restrict__ out,   // [rows][64]
                      int rows_total)
{
    __shared__ float Wt[67 * 64];     // Wt[c*64 + o] = W[o*67 + c]
    __shared__ float bsh[64];
    __shared__ float buf[16 * 64];    // per-warp 2-row feature sums

    const int tid = threadIdx.x;

    // Stage W transposed + bias into SMEM.
    for (int i = tid; i < 67 * 64; i += THREADS) {
        int o = i / 67;
        int c = i - o * 67;
        Wt[c * 64 + o] = W[i];
    }
    if (tid < 64) bsh[tid] = bias[tid];
    __syncthreads();

    const int warp = tid >> 5;
    const int lane = tid & 31;
    const int g    = lane >> 4;       // row group within warp (0/1)
    const int t    = lane & 15;       // channel-quad id (channels 4t..4t+3)
    const int slot = warp * 2 + g;

    const float4* Wt4 = reinterpret_cast<const float4*>(Wt);
    const float4  b4  = reinterpret_cast<const float4*>(bsh)[t];

    for (int chunk = 0; chunk < CHUNKS_PER_BLOCK; chunk++) {
        const int rowA = (blockIdx.x * CHUNKS_PER_BLOCK + chunk) * ROWS_PER_CHUNK
                         + warp * 2;
        if (rowA >= rows_total) break;
        const int row = rowA + g;
        const int b   = row >> LOG2_K;

        // --- per-lane neighbor metadata (lanes 0-15: rowA, lanes 16-31: rowA+1) ---
        const int   myidx = n_idxs[rowA * 32 / 2 + lane];        // rowA*16 + lane
        const float myval = (float)nvalid[rowA * 16 + lane];
        const float* relp = nrel + rowA * 48 + lane * 3;
        float r0 = relp[0] * myval;
        float r1 = relp[1] * myval;
        float r2 = relp[2] * myval;
        float cnt = myval;

        // butterfly reduce within 16-lane group (masks 1..8 stay in-group)
        #pragma unroll
        for (int m = 1; m < 16; m <<= 1) {
            r0  += __shfl_xor_sync(0xffffffffu, r0,  m);
            r1  += __shfl_xor_sync(0xffffffffu, r1,  m);
            r2  += __shfl_xor_sync(0xffffffffu, r2,  m);
            cnt += __shfl_xor_sync(0xffffffffu, cnt, m);
        }
        const float inv = (cnt > 0.0f) ? (1.0f / cnt) : 0.0f;

        // --- masked gather-sum of neighbor features (coalesced 256B per group) ---
        const float4* fb = reinterpret_cast<const float4*>(feats)
                           + ((size_t)b << LOG2_K) * 16;
        float4 acc = make_float4(0.f, 0.f, 0.f, 0.f);
        #pragma unroll
        for (int n = 0; n < 16; n++) {
            const int   src  = (lane & 16) + n;
            const int   idxn = __shfl_sync(0xffffffffu, myidx, src);
            const float vn   = __shfl_sync(0xffffffffu, myval, src);
            const float4 f = fb[(size_t)idxn * 16 + t];
            acc.x = fmaf(f.x, vn, acc.x);
            acc.y = fmaf(f.y, vn, acc.y);
            acc.z = fmaf(f.z, vn, acc.z);
            acc.w = fmaf(f.w, vn, acc.w);
        }

        // stage row sum for the per-row GEMM
        reinterpret_cast<float4*>(buf)[slot * 16 + t] = acc;
        __syncwarp();

        // --- 67x64 projection: out4[o] = sum_c sum[c] * Wt[c][o] ---
        const float* myrow = buf + slot * 64;
        float4 o4 = make_float4(0.f, 0.f, 0.f, 0.f);
        #pragma unroll
        for (int c = 0; c < 64; c++) {
            const float  s = myrow[c];          // LDS broadcast (2 addrs/warp)
            const float4 w = Wt4[c * 16 + t];   // conflict-free LDS.128
            o4.x = fmaf(s, w.x, o4.x);
            o4.y = fmaf(s, w.y, o4.y);
            o4.z = fmaf(s, w.z, o4.z);
            o4.w = fmaf(s, w.w, o4.w);
        }
        // rel channels 64..66 (srel already valid-masked, in registers)
        {
            const float4 w0 = Wt4[64 * 16 + t];
            const float4 w1 = Wt4[65 * 16 + t];
            const float4 w2 = Wt4[66 * 16 + t];
            o4.x = fmaf(r0, w0.x, o4.x); o4.y = fmaf(r0, w0.y, o4.y);
            o4.z = fmaf(r0, w0.z, o4.z); o4.w = fmaf(r0, w0.w, o4.w);
            o4.x = fmaf(r1, w1.x, o4.x); o4.y = fmaf(r1, w1.y, o4.y);
            o4.z = fmaf(r1, w1.z, o4.z); o4.w = fmaf(r1, w1.w, o4.w);
            o4.x = fmaf(r2, w2.x, o4.x); o4.y = fmaf(r2, w2.y, o4.y);
            o4.z = fmaf(r2, w2.z, o4.z); o4.w = fmaf(r2, w2.w, o4.w);
        }

        // epilogue: scale, bias, relu, store (coalesced 256B per group)
        float4 res;
        res.x = fmaxf(fmaf(o4.x, inv, b4.x), 0.0f);
        res.y = fmaxf(fmaf(o4.y, inv, b4.y), 0.0f);
        res.z = fmaxf(fmaf(o4.z, inv, b4.z), 0.0f);
        res.w = fmaxf(fmaf(o4.w, inv, b4.w), 0.0f);
        reinterpret_cast<float4*>(out)[(size_t)row * 16 + t] = res;

        __syncwarp();   // protect buf before next chunk rewrites it
    }
}

extern "C" void kernel_launch(void* const* d_in, const int* in_sizes, int n_in,
                              void* d_out, int out_size)
{
    // metadata order: keys, points, feats, n_idxs, neighbor_rel,
    //                 neighbor_valid, W, b
    const float* feats  = (const float*)d_in[2];
    const int*   n_idxs = (const int*)  d_in[3];
    const float* nrel   = (const float*)d_in[4];
    const int*   nvalid = (const int*)  d_in[5];
    const float* W      = (const float*)d_in[6];
    const float* bias   = (const float*)d_in[7];
    float*       out    = (float*)d_out;

    const int rows_total = out_size / 64;                 // B*K = 131072
    const int rows_per_block = CHUNKS_PER_BLOCK * ROWS_PER_CHUNK;  // 128
    const int grid = (rows_total + rows_per_block - 1) / rows_per_block;

    graphconv_kernel<<<grid, THREADS>>>(feats, n_idxs, nrel, nvalid,
                                        W, bias, out, rows_total);
}

// round 2
// speedup vs baseline: 1.2779x; 1.2779x over previous
#include <cuda_runtime.h>

// GraphConv split into 2 kernels:
//  K1: pf = feats @ W_feat^T   (dense SGEMM, [131072,64] x [64,64])
//  K2: out = relu( inv_cnt * ( sum_n valid_n * pf[idx_n] + srel . W_rel ) + b )
// Shapes fixed: B=8, P=K=16384, N=16, IN=64, REL=3, OUT=64.

#define LOG2_K 14
#define ROWS_TOTAL (8 * 16384)

__device__ float g_pf[(size_t)ROWS_TOTAL * 64];   // 32 MB scratch

// ---------------------------------------------------------------------------
// Kernel 1: register-blocked SGEMM. Block = 256 thr, tile 128 rows x 64 outs.
// Thread (i,j): rows 8i..8i+7, output quad j (cols 4j..4j+3). 2048 FMA/thread.
// SMEM: feats tile 128x64 (32KB) + Wt 64x64 (16KB) = 48KB exactly.
// ---------------------------------------------------------------------------
__global__ __launch_bounds__(256)
void proj_kernel(const float* __restrict__ feats,
                 const float* __restrict__ W,     // [64][67]
                 float*       __restrict__ pf)
{
    __shared__ float a_s[128 * 64];
    __shared__ float w_s[64 * 64];    // w_s[k*64+o] = W[o*67+k]

    const int tid = threadIdx.x;

    for (int idx = tid; idx < 64 * 64; idx += 256) {
        int o = idx >> 6, k = idx & 63;
        w_s[k * 64 + o] = W[o * 67 + k];
    }
    {
        const float4* fg = reinterpret_cast<const float4*>(feats)
                           + (size_t)blockIdx.x * (128 * 16);
        float4* a4 = reinterpret_cast<float4*>(a_s);
        #pragma unroll
        for (int s = 0; s < 8; s++) a4[s * 256 + tid] = fg[s * 256 + tid];
    }
    __syncthreads();

    const int j = tid & 15;     // output quad
    const int i = tid >> 4;     // row group (0..15)

    const float4* a4 = reinterpret_cast<const float4*>(a_s);
    const float4* w4 = reinterpret_cast<const float4*>(w_s);

    float4 acc[8];
    #pragma unroll
    for (int r = 0; r < 8; r++) acc[r] = make_float4(0.f, 0.f, 0.f, 0.f);

    #pragma unroll
    for (int kq = 0; kq < 16; kq++) {
        const float4 b0 = w4[(4 * kq + 0) * 16 + j];
        const float4 b1 = w4[(4 * kq + 1) * 16 + j];
        const float4 b2 = w4[(4 * kq + 2) * 16 + j];
        const float4 b3 = w4[(4 * kq + 3) * 16 + j];
        #pragma unroll
        for (int r = 0; r < 8; r++) {
            const float4 a = a4[(i * 8 + r) * 16 + kq];
            acc[r].x = fmaf(a.x, b0.x, acc[r].x); acc[r].y = fmaf(a.x, b0.y, acc[r].y);
            acc[r].z = fmaf(a.x, b0.z, acc[r].z); acc[r].w = fmaf(a.x, b0.w, acc[r].w);
            acc[r].x = fmaf(a.y, b1.x, acc[r].x); acc[r].y = fmaf(a.y, b1.y, acc[r].y);
            acc[r].z = fmaf(a.y, b1.z, acc[r].z); acc[r].w = fmaf(a.y, b1.w, acc[r].w);
            acc[r].x = fmaf(a.z, b2.x, acc[r].x); acc[r].y = fmaf(a.z, b2.y, acc[r].y);
            acc[r].z = fmaf(a.z, b2.z, acc[r].z); acc[r].w = fmaf(a.z, b2.w, acc[r].w);
            acc[r].x = fmaf(a.w, b3.x, acc[r].x); acc[r].y = fmaf(a.w, b3.y, acc[r].y);
            acc[r].z = fmaf(a.w, b3.z, acc[r].z); acc[r].w = fmaf(a.w, b3.w, acc[r].w);
        }
    }

    float4* pfo = reinterpret_cast<float4*>(pf)
                  + (size_t)blockIdx.x * (128 * 16);
    #pragma unroll
    for (int r = 0; r < 8; r++)
        pfo[(i * 8 + r) * 16 + j] = acc[r];
}

// ---------------------------------------------------------------------------
// Kernel 2: masked gather-sum over projected features + rel term + epilogue.
// 16 lanes per row (lane owns 4 outputs), 2 rows per warp.
// ---------------------------------------------------------------------------
#define THREADS 256
#define CHUNKS_PER_BLOCK 8
#define ROWS_PER_CHUNK 16

__global__ __launch_bounds__(THREADS)
void gather_kernel(const float* __restrict__ pf,
                   const int*   __restrict__ n_idxs,
                   const float* __restrict__ nrel,
                   const int*   __restrict__ nvalid,
                   const float* __restrict__ W,     // [64][67]
                   const float* __restrict__ bias,
                   float*       __restrict__ out,
                   int rows_total)
{
    __shared__ float wr_s[3 * 64];   // wr_s[jc*64+o] = W[o*67 + 64 + jc]
    __shared__ float b_s[64];

    const int tid = threadIdx.x;
    for (int i = tid; i < 192; i += THREADS) {
        int jc = i >> 6, o = i & 63;
        wr_s[i] = W[o * 67 + 64 + jc];
    }
    if (tid < 64) b_s[tid] = bias[tid];
    __syncthreads();

    const int warp = tid >> 5;
    const int lane = tid & 31;
    const int g    = lane >> 4;
    const int t    = lane & 15;

    const float4* wr4 = reinterpret_cast<const float4*>(wr_s);
    const float4  b4  = reinterpret_cast<const float4*>(b_s)[t];
    const float4  w0  = wr4[0 * 16 + t];
    const float4  w1  = wr4[1 * 16 + t];
    const float4  w2  = wr4[2 * 16 + t];

    for (int chunk = 0; chunk < CHUNKS_PER_BLOCK; chunk++) {
        const int rowA = (blockIdx.x * CHUNKS_PER_BLOCK + chunk) * ROWS_PER_CHUNK
                         + warp * 2;
        if (rowA >= rows_total) return;
        const int row = rowA + g;
        const int b   = row >> LOG2_K;

        // per-lane neighbor metadata: lanes 0-15 -> rowA, lanes 16-31 -> rowA+1
        const int   myidx = n_idxs[rowA * 16 + lane];
        const float myval = (float)nvalid[rowA * 16 + lane];
        const float* relp = nrel + rowA * 48 + lane * 3;
        float r0 = relp[0] * myval;
        float r1 = relp[1] * myval;
        float r2 = relp[2] * myval;
        float cnt = myval;

        #pragma unroll
        for (int m = 1; m < 16; m <<= 1) {
            r0  += __shfl_xor_sync(0xffffffffu, r0,  m);
            r1  += __shfl_xor_sync(0xffffffffu, r1,  m);
            r2  += __shfl_xor_sync(0xffffffffu, r2,  m);
            cnt += __shfl_xor_sync(0xffffffffu, cnt, m);
        }
        const float inv = (cnt > 0.0f) ? (1.0f / cnt) : 0.0f;

        // masked gather-sum of projected features (coalesced 256B per group)
        const float4* pb = reinterpret_cast<const float4*>(pf)
                           + ((size_t)b << LOG2_K) * 16;
        float4 acc = make_float4(0.f, 0.f, 0.f, 0.f);
        #pragma unroll
        for (int n = 0; n < 16; n++) {
            const int   src  = (lane & 16) + n;
            const int   idxn = __shfl_sync(0xffffffffu, myidx, src);
            const float vn   = __shfl_sync(0xffffffffu, myval, src);
            const float4 f = pb[(size_t)idxn * 16 + t];
            acc.x = fmaf(f.x, vn, acc.x);
            acc.y = fmaf(f.y, vn, acc.y);
            acc.z = fmaf(f.z, vn, acc.z);
            acc.w = fmaf(f.w, vn, acc.w);
        }

        // rel-channel contribution (already valid-masked)
        acc.x = fmaf(r0, w0.x, acc.x); acc.y = fmaf(r0, w0.y, acc.y);
        acc.z = fmaf(r0, w0.z, acc.z); acc.w = fmaf(r0, w0.w, acc.w);
        acc.x = fmaf(r1, w1.x, acc.x); acc.y = fmaf(r1, w1.y, acc.y);
        acc.z = fmaf(r1, w1.z, acc.z); acc.w = fmaf(r1, w1.w, acc.w);
        acc.x = fmaf(r2, w2.x, acc.x); acc.y = fmaf(r2, w2.y, acc.y);
        acc.z = fmaf(r2, w2.z, acc.z); acc.w = fmaf(r2, w2.w, acc.w);

        float4 res;
        res.x = fmaxf(fmaf(acc.x, inv, b4.x), 0.0f);
        res.y = fmaxf(fmaf(acc.y, inv, b4.y), 0.0f);
        res.z = fmaxf(fmaf(acc.z, inv, b4.z), 0.0f);
        res.w = fmaxf(fmaf(acc.w, inv, b4.w), 0.0f);
        reinterpret_cast<float4*>(out)[(size_t)row * 16 + t] = res;
    }
}

extern "C" void kernel_launch(void* const* d_in, const int* in_sizes, int n_in,
                              void* d_out, int out_size)
{
    // metadata order: keys, points, feats, n_idxs, neighbor_rel,
    //                 neighbor_valid, W, b
    const float* feats  = (const float*)d_in[2];
    const int*   n_idxs = (const int*)  d_in[3];
    const float* nrel   = (const float*)d_in[4];
    const int*   nvalid = (const int*)  d_in[5];
    const float* W      = (const float*)d_in[6];
    const float* bias   = (const float*)d_in[7];
    float*       out    = (float*)d_out;

    const int rows_total = out_size / 64;   // 131072

    float* pf = nullptr;
    cudaGetSymbolAddress((void**)&pf, g_pf);

    proj_kernel<<<rows_total / 128, 256>>>(feats, W, pf);

    const int rows_per_block = CHUNKS_PER_BLOCK * ROWS_PER_CHUNK;
    const int grid = (rows_total + rows_per_block - 1) / rows_per_block;
    gather_kernel<<<grid, THREADS>>>(pf, n_idxs, nrel, nvalid,
                                     W, bias, out, rows_total);
}